// round 2
// baseline (speedup 1.0000x reference)
#include <cuda_runtime.h>
#include <cuda_bf16.h>
#include <cstdint>

#define N_NODES 50000
#define N_EDGES 800000
#define IN_DIM  256
#define OUT_DIM 64

// Scratch for support = X @ W  (12.8 MB) — __device__ global per allocation rules.
__device__ float g_support[(size_t)N_NODES * OUT_DIM];

// ---------------------------------------------------------------------------
// Kernel 1: out[n, :] = bias[:]   (output init before scatter-add)
// ---------------------------------------------------------------------------
__global__ __launch_bounds__(256) void init_out_kernel(const float* __restrict__ bias,
                                                       float* __restrict__ out) {
    int i = blockIdx.x * blockDim.x + threadIdx.x;            // float4 index
    const int total4 = N_NODES * OUT_DIM / 4;                 // 800000
    if (i < total4) {
        float4 b = reinterpret_cast<const float4*>(bias)[i & 15];
        reinterpret_cast<float4*>(out)[i] = b;
    }
}

// ---------------------------------------------------------------------------
// Kernel 2: support = X @ W   (M=50000, K=256, N=64)
// Block tile: 64 rows x 64 cols, 256 threads, 4x4 micro-tile per thread,
// packed f32x2 FMAs (2 cols per instruction).
// ---------------------------------------------------------------------------
__global__ __launch_bounds__(256) void gemm_kernel(const float* __restrict__ X,
                                                   const float* __restrict__ W) {
    __shared__ float sAT[64][68];   // [k][row], padded row stride (16B-aligned)
    __shared__ float sW[64][64];    // [k][col]

    const int tid = threadIdx.x;
    const int tx  = tid & 15;       // col group (4 cols each)
    const int ty  = tid >> 4;       // row group (4 rows each)
    const int row0 = blockIdx.x * 64;

    unsigned long long acc[4][2];
#pragma unroll
    for (int i = 0; i < 4; i++) { acc[i][0] = 0ULL; acc[i][1] = 0ULL; }

    for (int kc = 0; kc < IN_DIM; kc += 64) {
        // --- load A tile (64 rows x 64 k) transposed into sAT[k][row] ---
        {
            const int r  = tid & 63;
            const int kg = tid >> 6;      // 0..3
            const int grow = row0 + r;
#pragma unroll
            for (int j = 0; j < 4; j++) {
                const int k4 = kg + j * 4;      // float4 index along k (0..15)
                float4 v = make_float4(0.f, 0.f, 0.f, 0.f);
                if (grow < N_NODES)
                    v = *reinterpret_cast<const float4*>(
                        X + (size_t)grow * IN_DIM + kc + k4 * 4);
                sAT[k4 * 4 + 0][r] = v.x;
                sAT[k4 * 4 + 1][r] = v.y;
                sAT[k4 * 4 + 2][r] = v.z;
                sAT[k4 * 4 + 3][r] = v.w;
            }
        }
        // --- load W tile (64 k x 64 cols) into sW[k][col] ---
        {
            const int c4 = tid & 15;
            const int kk = tid >> 4;      // 0..15
#pragma unroll
            for (int j = 0; j < 4; j++) {
                const int k = kk + j * 16;
                float4 v = *reinterpret_cast<const float4*>(
                    W + (size_t)(kc + k) * OUT_DIM + c4 * 4);
                *reinterpret_cast<float4*>(&sW[k][c4 * 4]) = v;
            }
        }
        __syncthreads();

#pragma unroll
        for (int kk = 0; kk < 64; kk++) {
            float4 a = *reinterpret_cast<const float4*>(&sAT[kk][ty * 4]);
            float4 b = *reinterpret_cast<const float4*>(&sW[kk][tx * 4]);
            unsigned long long b01, b23;
            asm("mov.b64 %0, {%1,%2};" : "=l"(b01)
                : "r"(__float_as_uint(b.x)), "r"(__float_as_uint(b.y)));
            asm("mov.b64 %0, {%1,%2};" : "=l"(b23)
                : "r"(__float_as_uint(b.z)), "r"(__float_as_uint(b.w)));
            float ar[4] = {a.x, a.y, a.z, a.w};
#pragma unroll
            for (int i = 0; i < 4; i++) {
                unsigned long long aa;
                asm("mov.b64 %0, {%1,%1};" : "=l"(aa)
                    : "r"(__float_as_uint(ar[i])));
                asm("fma.rn.f32x2 %0, %1, %2, %0;"
                    : "+l"(acc[i][0]) : "l"(aa), "l"(b01));
                asm("fma.rn.f32x2 %0, %1, %2, %0;"
                    : "+l"(acc[i][1]) : "l"(aa), "l"(b23));
            }
        }
        __syncthreads();
    }

    // --- store 4x4 micro-tile ---
#pragma unroll
    for (int i = 0; i < 4; i++) {
        const int grow = row0 + ty * 4 + i;
        if (grow < N_NODES) {
            unsigned int x0, x1, x2, x3;
            asm("mov.b64 {%0,%1}, %2;" : "=r"(x0), "=r"(x1) : "l"(acc[i][0]));
            asm("mov.b64 {%0,%1}, %2;" : "=r"(x2), "=r"(x3) : "l"(acc[i][1]));
            float4 o = make_float4(__uint_as_float(x0), __uint_as_float(x1),
                                   __uint_as_float(x2), __uint_as_float(x3));
            *reinterpret_cast<float4*>(g_support + (size_t)grow * OUT_DIM + tx * 4) = o;
        }
    }
}

// ---------------------------------------------------------------------------
// Kernel 3: scatter-add.  16 threads per edge; each thread handles one float4
// of the 64-wide row: gather from support[src], scale by edge_val, vector
// atomic add (red.global.add.v4.f32, sm_90+) into out[dst].
// Edge indices are int32 (JAX demotes int64 without x64 mode).
// ---------------------------------------------------------------------------
__global__ __launch_bounds__(256) void scatter_kernel(const float* __restrict__ edge_val,
                                                      const int* __restrict__ edge_src,
                                                      const int* __restrict__ edge_dst,
                                                      float* __restrict__ out) {
    const int t = blockIdx.x * blockDim.x + threadIdx.x;
    const int e = t >> 4;
    const int lane = t & 15;
    if (e >= N_EDGES) return;

    const int s = edge_src[e];
    const int d = edge_dst[e];
    const float v = edge_val[e];

    float4 m = reinterpret_cast<const float4*>(g_support + (size_t)s * OUT_DIM)[lane];
    m.x *= v; m.y *= v; m.z *= v; m.w *= v;

    float* o = out + (size_t)d * OUT_DIM + lane * 4;
    asm volatile("red.global.add.v4.f32 [%0], {%1,%2,%3,%4};"
                 :: "l"(o), "f"(m.x), "f"(m.y), "f"(m.z), "f"(m.w)
                 : "memory");
}

// ---------------------------------------------------------------------------
extern "C" void kernel_launch(void* const* d_in, const int* in_sizes, int n_in,
                              void* d_out, int out_size) {
    const float* X    = (const float*)d_in[0];     // [50000, 256]
    const float* W    = (const float*)d_in[1];     // [256, 64]
    const float* bias = (const float*)d_in[2];     // [64]
    const float* ev   = (const float*)d_in[3];     // [800000]
    const int*   es   = (const int*)d_in[4];       // [800000] int32
    const int*   ed   = (const int*)d_in[5];       // [800000] int32
    float* out = (float*)d_out;                    // [50000, 64]

    // init output with bias (independent of GEMM)
    {
        const int total4 = N_NODES * OUT_DIM / 4;
        init_out_kernel<<<(total4 + 255) / 256, 256>>>(bias, out);
    }
    // support = X @ W
    {
        const int grid = (N_NODES + 63) / 64;
        gemm_kernel<<<grid, 256>>>(X, W);
    }
    // scatter-add over edges
    {
        const long long threads = (long long)N_EDGES * 16;
        const int grid = (int)((threads + 255) / 256);
        scatter_kernel<<<grid, 256>>>(ev, es, ed, out);
    }
}